// round 12
// baseline (speedup 1.0000x reference)
#include <cuda_runtime.h>
#include <cuda_bf16.h>

#define N_NODES 100000
#define N_EDGES 3200000
#define HID     128
#define N_GRAPHS 128
#define BN_EPS  1e-5f
#define SCAN_BLOCKS 98   // 98 * 1024 = 100352 >= N_NODES

typedef unsigned long long ull;

// ---------------- device scratch (static, no allocation) ----------------
__device__ unsigned g_yb[(size_t)N_NODES * 64];  // y = x @ W1 (bf16x2); scaled in-place to dinv*y
__device__ unsigned g_hb[(size_t)N_NODES * 64];  // hs = dinv*relu(BN(..)), packed bf16x2
__device__ int   g_cnt_node[N_NODES];            // in-degree histogram
__device__ int   g_rowptr[N_NODES + 1];
__device__ int   g_cursor[N_NODES];
__device__ int   g_col[N_EDGES];                 // CSR column (src) indices, by dst
__device__ float g_dinv[N_NODES];
__device__ float g_pool[N_GRAPHS * HID];         // P[g] = sum_v dinv_v * agg_h(v)
__device__ int   g_gcnt[N_GRAPHS];
__device__ int   g_bsum[SCAN_BLOCKS];
__device__ int   g_boff[SCAN_BLOCKS];

// ---------------- f32x2 / bf16 helpers (sm_10x packed fp32 pipe) ----------------
__device__ __forceinline__ ull pack2(float v) {
    ull r; asm("mov.b64 %0, {%1, %1};" : "=l"(r) : "f"(v)); return r;
}
__device__ __forceinline__ void fma2(ull &d, ull a, ull b) {
    asm("fma.rn.f32x2 %0, %1, %2, %0;" : "+l"(d) : "l"(a), "l"(b));
}
__device__ __forceinline__ void add2(ull &d, ull a) {
    asm("add.rn.f32x2 %0, %0, %1;" : "+l"(d) : "l"(a));
}
__device__ __forceinline__ void unpack2(ull v, float &lo, float &hi) {
    asm("mov.b64 {%0, %1}, %2;" : "=f"(lo), "=f"(hi) : "l"(v));
}
// bf16x2 word -> f32x2 pair {f32(lo bf16), f32(hi bf16)} via shifts (bf16 = high 16 bits of f32)
__device__ __forceinline__ ull bf2f2(unsigned p) {
    unsigned lo = p << 16;
    unsigned hi = p & 0xFFFF0000u;
    ull r; asm("mov.b64 %0, {%1, %2};" : "=l"(r) : "r"(lo), "r"(hi));
    return r;
}

// ---------------- zero per-replay accumulators ----------------
__global__ void zero_kernel() {
    int i = blockIdx.x * blockDim.x + threadIdx.x;
    int stride = gridDim.x * blockDim.x;
    int4* c4 = (int4*)g_cnt_node;
    int4 z4 = make_int4(0, 0, 0, 0);
    for (int k = i; k < N_NODES / 4; k += stride) c4[k] = z4;
    for (int k = i; k < N_GRAPHS * HID; k += stride) g_pool[k] = 0.0f;
}

// ---------------- in-degree histogram: 4 edges per thread ----------------
__global__ void hist_edges_kernel(const int* __restrict__ dst) {
    int i = blockIdx.x * blockDim.x + threadIdx.x;
    if (i < N_EDGES / 4) {
        int4 d4 = ((const int4*)dst)[i];
        atomicAdd(&g_cnt_node[d4.x], 1);
        atomicAdd(&g_cnt_node[d4.y], 1);
        atomicAdd(&g_cnt_node[d4.z], 1);
        atomicAdd(&g_cnt_node[d4.w], 1);
    }
}

// ---------------- per-graph counts via binary search (batch is sorted) --------------
__global__ void gcnt_kernel(const int* __restrict__ batch) {
    __shared__ int starts[N_GRAPHS + 1];
    int g = threadIdx.x;
    if (g <= N_GRAPHS) {
        int lo = 0, hi = N_NODES;
        while (lo < hi) {
            int mid = (lo + hi) >> 1;
            if (batch[mid] < g) lo = mid + 1; else hi = mid;
        }
        starts[g] = lo;
    }
    __syncthreads();
    if (g < N_GRAPHS) g_gcnt[g] = starts[g + 1] - starts[g];
}

// ---------------- parallel scan phase A ----------------
__global__ __launch_bounds__(1024) void scanA_kernel() {
    __shared__ int wsum[32];
    int tid = threadIdx.x, lane = tid & 31, wid = tid >> 5;
    int i = blockIdx.x * 1024 + tid;
    int v = (i < N_NODES) ? g_cnt_node[i] : 0;
    int x = v;
    #pragma unroll
    for (int off = 1; off < 32; off <<= 1) {
        int t = __shfl_up_sync(0xffffffffu, x, off);
        if (lane >= off) x += t;
    }
    if (lane == 31) wsum[wid] = x;
    __syncthreads();
    if (wid == 0) {
        int s = wsum[lane];
        #pragma unroll
        for (int off = 1; off < 32; off <<= 1) {
            int t = __shfl_up_sync(0xffffffffu, s, off);
            if (lane >= off) s += t;
        }
        wsum[lane] = s;
    }
    __syncthreads();
    int woff = (wid == 0) ? 0 : wsum[wid - 1];
    if (i < N_NODES) {
        g_rowptr[i] = woff + (x - v);
        g_dinv[i]   = rsqrtf((float)(v + 1));
    }
    if (tid == 1023) g_bsum[blockIdx.x] = wsum[31];
}

// ---------------- scan phase B ----------------
__global__ void scanB_kernel() {
    __shared__ int wsum[4];
    int tid = threadIdx.x, lane = tid & 31, wid = tid >> 5;
    int v = (tid < SCAN_BLOCKS) ? g_bsum[tid] : 0;
    int x = v;
    #pragma unroll
    for (int off = 1; off < 32; off <<= 1) {
        int t = __shfl_up_sync(0xffffffffu, x, off);
        if (lane >= off) x += t;
    }
    if (lane == 31) wsum[wid] = x;
    __syncthreads();
    int woff = 0;
    for (int w = 0; w < wid; w++) woff += wsum[w];
    if (tid < SCAN_BLOCKS) g_boff[tid] = woff + (x - v);
    if (tid == 0) g_rowptr[N_NODES] = N_EDGES;
}

// ---------------- scan phase C ----------------
__global__ __launch_bounds__(1024) void scanC_kernel() {
    int i = blockIdx.x * 1024 + threadIdx.x;
    if (i < N_NODES) {
        int r = g_rowptr[i] + g_boff[blockIdx.x];
        g_rowptr[i] = r;
        g_cursor[i] = r;
    }
}

// ---------------- CSR fill, 4 edges per thread -------------
__global__ void fill_kernel(const int* __restrict__ src,
                            const int* __restrict__ dst) {
    int i = blockIdx.x * blockDim.x + threadIdx.x;
    if (i < N_EDGES / 4) {
        int4 s4 = ((const int4*)src)[i];
        int4 d4 = ((const int4*)dst)[i];
        int p0 = atomicAdd(&g_cursor[d4.x], 1);
        int p1 = atomicAdd(&g_cursor[d4.y], 1);
        int p2 = atomicAdd(&g_cursor[d4.z], 1);
        int p3 = atomicAdd(&g_cursor[d4.w], 1);
        g_col[p0] = s4.x;
        g_col[p1] = s4.y;
        g_col[p2] = s4.z;
        g_col[p3] = s4.w;
    }
}

// ---- fp32 GEMM (f32x2 pipe): y[r] = X[r] @ W, output packed bf16x2 -----------------
__global__ __launch_bounds__(256) void gemm128_kernel(const float* __restrict__ X,
                                                      const float* __restrict__ W,
                                                      int nrows) {
    __shared__ float As[16][128];
    __shared__ float Bs[16][128];
    int tid = threadIdx.x;
    int tx = tid & 15, ty = tid >> 4;
    int row0 = blockIdx.x * 128;

    ull acc2[8][4];
    #pragma unroll
    for (int j = 0; j < 8; j++)
        #pragma unroll
        for (int i2 = 0; i2 < 4; i2++) acc2[j][i2] = 0ull;

    for (int k0 = 0; k0 < 128; k0 += 16) {
        {
            int r  = tid >> 2;
            int kk = (tid & 3) * 4;
            #pragma unroll
            for (int rr = r; rr < 128; rr += 64) {
                int grow = row0 + rr;
                float4 v = make_float4(0.f, 0.f, 0.f, 0.f);
                if (grow < nrows) v = *(const float4*)(X + (size_t)grow * 128 + k0 + kk);
                As[kk + 0][rr] = v.x; As[kk + 1][rr] = v.y;
                As[kk + 2][rr] = v.z; As[kk + 3][rr] = v.w;
            }
            int k  = tid >> 5;
            int cc = (tid & 31) * 4;
            #pragma unroll
            for (int kk2 = k; kk2 < 16; kk2 += 8) {
                *(float4*)&Bs[kk2][cc] = *(const float4*)(W + (size_t)(k0 + kk2) * 128 + cc);
            }
        }
        __syncthreads();
        #pragma unroll
        for (int k = 0; k < 16; k++) {
            ull a2[4];
            const float* ar = &As[k][0];
            a2[0] = *(const ull*)(ar + ty * 4);
            a2[1] = *(const ull*)(ar + ty * 4 + 2);
            a2[2] = *(const ull*)(ar + 64 + ty * 4);
            a2[3] = *(const ull*)(ar + 64 + ty * 4 + 2);
            ull bb[8];
            #pragma unroll
            for (int j = 0; j < 4; j++) {
                bb[j]     = pack2(Bs[k][tx * 4 + j]);
                bb[4 + j] = pack2(Bs[k][64 + tx * 4 + j]);
            }
            #pragma unroll
            for (int j = 0; j < 8; j++)
                #pragma unroll
                for (int i2 = 0; i2 < 4; i2++)
                    fma2(acc2[j][i2], a2[i2], bb[j]);
        }
        __syncthreads();
    }
    float accf[8][8];
    #pragma unroll
    for (int i2 = 0; i2 < 4; i2++) {
        int iiL = (i2 < 2) ? (i2 * 2) : (4 + (i2 - 2) * 2);
        #pragma unroll
        for (int j = 0; j < 8; j++)
            unpack2(acc2[j][i2], accf[iiL][j], accf[iiL + 1][j]);
    }
    #pragma unroll
    for (int ii = 0; ii < 8; ii++) {
        int r = row0 + ((ii < 4) ? (ty * 4 + ii) : (64 + ty * 4 + (ii - 4)));
        if (r < nrows) {
            __nv_bfloat162 q0 = __floats2bfloat162_rn(accf[ii][0], accf[ii][1]);
            __nv_bfloat162 q1 = __floats2bfloat162_rn(accf[ii][2], accf[ii][3]);
            __nv_bfloat162 q2 = __floats2bfloat162_rn(accf[ii][4], accf[ii][5]);
            __nv_bfloat162 q3 = __floats2bfloat162_rn(accf[ii][6], accf[ii][7]);
            uint2 lo, hi;
            lo.x = *(unsigned*)&q0; lo.y = *(unsigned*)&q1;
            hi.x = *(unsigned*)&q2; hi.y = *(unsigned*)&q3;
            *(uint2*)(g_yb + (size_t)r * 64 + tx * 2)      = lo;
            *(uint2*)(g_yb + (size_t)r * 64 + 32 + tx * 2) = hi;
        }
    }
}

// ---- scale_y: g_yb[v] *= dinv[v] (in place, bf16) ----------------------------------
__global__ __launch_bounds__(256) void scale_y_kernel() {
    int i = blockIdx.x * blockDim.x + threadIdx.x;  // uint2 index; total N_NODES*32
    if (i < N_NODES * 32) {
        int v = i >> 5;
        float dv = g_dinv[v];
        uint2* p = (uint2*)g_yb + i;
        uint2 pk = *p;
        float2 f0 = __bfloat1622float2(*(__nv_bfloat162*)&pk.x);
        float2 f1 = __bfloat1622float2(*(__nv_bfloat162*)&pk.y);
        __nv_bfloat162 q0 = __floats2bfloat162_rn(dv * f0.x, dv * f0.y);
        __nv_bfloat162 q1 = __floats2bfloat162_rn(dv * f1.x, dv * f1.y);
        pk.x = *(unsigned*)&q0;
        pk.y = *(unsigned*)&q1;
        *p = pk;
    }
}

// ---- agg1 (bf16 gather, ys pre-scaled): hs[v] = dinv_v*relu(BN(dv*sum + b1)) -------
__global__ __launch_bounds__(256) void agg1_kernel(const float* __restrict__ b1,
                                                   const float* __restrict__ gamma,
                                                   const float* __restrict__ beta,
                                                   const float* __restrict__ rmean,
                                                   const float* __restrict__ rvar) {
    int gw = (blockIdx.x * blockDim.x + threadIdx.x) >> 5;
    int lane = threadIdx.x & 31;
    if (gw >= N_NODES) return;
    int v = gw;
    int cb = lane * 4;
    const unsigned* __restrict__ ys = (const unsigned*)g_yb;
    ull acc0, acc1;
    {
        uint2 pk = *(const uint2*)(ys + (size_t)v * 64 + lane * 2);
        acc0 = bf2f2(pk.x);           // self term = dinv_v * y_v (pre-scaled)
        acc1 = bf2f2(pk.y);
    }
    int s = g_rowptr[v], e = g_rowptr[v + 1];
    int j = s;
    for (; j + 32 <= e; j += 32) {
        int c = g_col[j + lane];
        #pragma unroll
        for (int t = 0; t < 32; t += 4) {
            int u0 = __shfl_sync(0xffffffffu, c, t);
            int u1 = __shfl_sync(0xffffffffu, c, t + 1);
            int u2 = __shfl_sync(0xffffffffu, c, t + 2);
            int u3 = __shfl_sync(0xffffffffu, c, t + 3);
            uint2 pa = *(const uint2*)(ys + (size_t)u0 * 64 + lane * 2);
            uint2 pb = *(const uint2*)(ys + (size_t)u1 * 64 + lane * 2);
            uint2 pc = *(const uint2*)(ys + (size_t)u2 * 64 + lane * 2);
            uint2 pd = *(const uint2*)(ys + (size_t)u3 * 64 + lane * 2);
            add2(acc0, bf2f2(pa.x)); add2(acc1, bf2f2(pa.y));
            add2(acc0, bf2f2(pb.x)); add2(acc1, bf2f2(pb.y));
            add2(acc0, bf2f2(pc.x)); add2(acc1, bf2f2(pc.y));
            add2(acc0, bf2f2(pd.x)); add2(acc1, bf2f2(pd.y));
        }
    }
    if (j < e) {
        int c = (j + lane < e) ? g_col[j + lane] : 0;
        int n = e - j;
        for (int t = 0; t < n; t++) {
            int u = __shfl_sync(0xffffffffu, c, t);
            uint2 pk = *(const uint2*)(ys + (size_t)u * 64 + lane * 2);
            add2(acc0, bf2f2(pk.x));
            add2(acc1, bf2f2(pk.y));
        }
    }
    float dv = g_dinv[v];
    float a0, a1, a2v, a3;
    unpack2(acc0, a0, a1);
    unpack2(acc1, a2v, a3);
    float4 bb = *(const float4*)(b1 + cb);
    float4 gm = *(const float4*)(gamma + cb);
    float4 bt = *(const float4*)(beta + cb);
    float4 rm = *(const float4*)(rmean + cb);
    float4 rv = *(const float4*)(rvar + cb);
    float o0, o1, o2, o3;
    {
        float t0 = a0 * dv + bb.x;
        float t1 = a1 * dv + bb.y;
        float t2 = a2v * dv + bb.z;
        float t3 = a3 * dv + bb.w;
        o0 = dv * fmaxf((t0 - rm.x) * rsqrtf(rv.x + BN_EPS) * gm.x + bt.x, 0.0f);
        o1 = dv * fmaxf((t1 - rm.y) * rsqrtf(rv.y + BN_EPS) * gm.y + bt.y, 0.0f);
        o2 = dv * fmaxf((t2 - rm.z) * rsqrtf(rv.z + BN_EPS) * gm.z + bt.z, 0.0f);
        o3 = dv * fmaxf((t3 - rm.w) * rsqrtf(rv.w + BN_EPS) * gm.w + bt.w, 0.0f);
    }
    __nv_bfloat162 p0 = __floats2bfloat162_rn(o0, o1);
    __nv_bfloat162 p1 = __floats2bfloat162_rn(o2, o3);
    uint2 pk;
    pk.x = *(unsigned*)&p0;
    pk.y = *(unsigned*)&p1;
    *(uint2*)(g_hb + (size_t)v * 64 + lane * 2) = pk;
}

// ---- agg2 (bf16 gather): P[batch[v]] += dinv_v * (sum_u hs_u + hs_v) ---------------
__global__ __launch_bounds__(256) void agg2_kernel(const int* __restrict__ batch) {
    int gw = (blockIdx.x * blockDim.x + threadIdx.x) >> 5;
    int lane = threadIdx.x & 31;
    if (gw >= N_NODES) return;
    int v = gw;
    const unsigned* __restrict__ hb = (const unsigned*)g_hb;
    ull acc0, acc1;
    {
        uint2 pk = *(const uint2*)(hb + (size_t)v * 64 + lane * 2);
        acc0 = bf2f2(pk.x);           // self term = hs_v
        acc1 = bf2f2(pk.y);
    }
    int s = g_rowptr[v], e = g_rowptr[v + 1];
    int j = s;
    for (; j + 32 <= e; j += 32) {
        int c = g_col[j + lane];
        #pragma unroll
        for (int t = 0; t < 32; t += 4) {
            int u0 = __shfl_sync(0xffffffffu, c, t);
            int u1 = __shfl_sync(0xffffffffu, c, t + 1);
            int u2 = __shfl_sync(0xffffffffu, c, t + 2);
            int u3 = __shfl_sync(0xffffffffu, c, t + 3);
            uint2 pa = *(const uint2*)(hb + (size_t)u0 * 64 + lane * 2);
            uint2 pb = *(const uint2*)(hb + (size_t)u1 * 64 + lane * 2);
            uint2 pc = *(const uint2*)(hb + (size_t)u2 * 64 + lane * 2);
            uint2 pd = *(const uint2*)(hb + (size_t)u3 * 64 + lane * 2);
            add2(acc0, bf2f2(pa.x)); add2(acc1, bf2f2(pa.y));
            add2(acc0, bf2f2(pb.x)); add2(acc1, bf2f2(pb.y));
            add2(acc0, bf2f2(pc.x)); add2(acc1, bf2f2(pc.y));
            add2(acc0, bf2f2(pd.x)); add2(acc1, bf2f2(pd.y));
        }
    }
    if (j < e) {
        int c = (j + lane < e) ? g_col[j + lane] : 0;
        int n = e - j;
        for (int t = 0; t < n; t++) {
            int u = __shfl_sync(0xffffffffu, c, t);
            uint2 pk = *(const uint2*)(hb + (size_t)u * 64 + lane * 2);
            add2(acc0, bf2f2(pk.x));
            add2(acc1, bf2f2(pk.y));
        }
    }
    float dv = g_dinv[v];
    float a0, a1, a2v, a3;
    unpack2(acc0, a0, a1);
    unpack2(acc1, a2v, a3);
    int g = batch[v];
    float* pp = g_pool + (size_t)g * 128 + lane * 4;
    atomicAdd(pp + 0, a0 * dv);
    atomicAdd(pp + 1, a1 * dv);
    atomicAdd(pp + 2, a2v * dv);
    atomicAdd(pp + 3, a3 * dv);
}

// ---- head: per graph: pooled = (P/cnt)@W2 + b2 ; z = relu(pooled@fw1+fb1) ; out ----
__global__ __launch_bounds__(128) void head_kernel(const float* __restrict__ W2,
                                                   const float* __restrict__ b2,
                                                   const float* __restrict__ fw1,
                                                   const float* __restrict__ fb1,
                                                   const float* __restrict__ cw,
                                                   const float* __restrict__ cbp,
                                                   float* __restrict__ out) {
    __shared__ float Ps[128];
    __shared__ float pooled[128];
    __shared__ float z[64];
    int g = blockIdx.x;
    int j = threadIdx.x;
    float ic = 1.0f / fmaxf((float)g_gcnt[g], 1.0f);
    Ps[j] = g_pool[(size_t)g * 128 + j] * ic;
    __syncthreads();
    float sacc = b2[j];
    #pragma unroll 8
    for (int k = 0; k < 128; k++) sacc = fmaf(Ps[k], W2[(size_t)k * 128 + j], sacc);
    pooled[j] = sacc;
    __syncthreads();
    if (j < 64) {
        float t = fb1[j];
        #pragma unroll 8
        for (int k = 0; k < 128; k++) t = fmaf(pooled[k], fw1[(size_t)k * 64 + j], t);
        z[j] = fmaxf(t, 0.0f);
    }
    __syncthreads();
    if (j < 2) {
        float o = cbp[j];
        #pragma unroll
        for (int jj = 0; jj < 64; jj++) o = fmaf(z[jj], cw[jj * 2 + j], o);
        out[g * 2 + j] = o;
    }
}

// ---------------- launch ----------------
extern "C" void kernel_launch(void* const* d_in, const int* in_sizes, int n_in,
                              void* d_out, int out_size) {
    const float* x     = (const float*)d_in[0];
    const int*   eidx  = (const int*)d_in[1];
    const int*   batch = (const int*)d_in[2];
    const float* W1    = (const float*)d_in[3];
    const float* b1    = (const float*)d_in[4];
    const float* gamma = (const float*)d_in[5];
    const float* beta  = (const float*)d_in[6];
    const float* rmean = (const float*)d_in[7];
    const float* rvar  = (const float*)d_in[8];
    const float* W2    = (const float*)d_in[9];
    const float* b2    = (const float*)d_in[10];
    const float* fw1   = (const float*)d_in[11];
    const float* fb1   = (const float*)d_in[12];
    const float* cw    = (const float*)d_in[13];
    const float* cbv   = (const float*)d_in[14];
    float* out = (float*)d_out;

    const int* src = eidx;
    const int* dst = eidx + N_EDGES;

    cudaStream_t s2;
    cudaStreamCreateWithFlags(&s2, cudaStreamNonBlocking);
    cudaEvent_t e1, e2;
    cudaEventCreateWithFlags(&e1, cudaEventDisableTiming);
    cudaEventCreateWithFlags(&e2, cudaEventDisableTiming);

    // fork: gemm1 + gcnt depend only on inputs
    cudaEventRecord(e1, 0);
    cudaStreamWaitEvent(s2, e1, 0);
    gemm128_kernel<<<(N_NODES + 127) / 128, 256, 0, s2>>>(x, W1, N_NODES);
    gcnt_kernel<<<1, N_GRAPHS + 1, 0, s2>>>(batch);

    // CSR build on main stream, concurrent with gemm1
    zero_kernel<<<256, 256>>>();
    hist_edges_kernel<<<(N_EDGES / 4 + 255) / 256, 256>>>(dst);
    scanA_kernel<<<SCAN_BLOCKS, 1024>>>();
    scanB_kernel<<<1, 128>>>();
    scanC_kernel<<<SCAN_BLOCKS, 1024>>>();
    fill_kernel<<<(N_EDGES / 4 + 255) / 256, 256>>>(src, dst);

    // join
    cudaEventRecord(e2, s2);
    cudaStreamWaitEvent(0, e2, 0);

    // pre-scale y by dinv (kills per-edge dinv loads in agg1)
    scale_y_kernel<<<(N_NODES * 32 + 255) / 256, 256>>>();

    // layer 1 aggregation (bf16 gather + BN + relu), bf16 output
    agg1_kernel<<<(N_NODES + 7) / 8, 256>>>(b1, gamma, beta, rmean, rvar);

    // layer 2 aggregation (bf16 gather) directly into per-graph pool
    agg2_kernel<<<(N_NODES + 7) / 8, 256>>>(batch);

    // head: W2 + mean + MLP
    head_kernel<<<N_GRAPHS, 128>>>(W2, b2, fw1, fb1, cw, cbv, out);

    cudaEventDestroy(e1);
    cudaEventDestroy(e2);
    cudaStreamDestroy(s2);
}

// round 14
// speedup vs baseline: 1.0966x; 1.0966x over previous
#include <cuda_runtime.h>
#include <cuda_bf16.h>

#define N_NODES 100000
#define N_EDGES 3200000
#define HID     128
#define N_GRAPHS 128
#define BN_EPS  1e-5f
#define SCAN_BLOCKS 98   // 98 * 1024 = 100352 >= N_NODES

typedef unsigned long long ull;

// ---------------- device scratch (static, no allocation) ----------------
__device__ unsigned g_yb[(size_t)N_NODES * 64];  // y = x @ W1 (bf16x2); scaled in place to dinv*y
__device__ unsigned g_hb[(size_t)N_NODES * 64];  // hs = dinv*relu(BN(..)), packed bf16x2
__device__ int   g_cnt_node[N_NODES];            // in-degree histogram
__device__ int   g_rowptr[N_NODES + 1];
__device__ int   g_cursor[N_NODES];
__device__ int   g_col[N_EDGES];                 // CSR column (src) indices, by dst
__device__ float g_dinv[N_NODES];
__device__ float g_pool[N_GRAPHS * HID];         // P[g] = sum_v dinv_v * agg_h(v)
__device__ int   g_gcnt[N_GRAPHS];
__device__ int   g_bsum[SCAN_BLOCKS];
__device__ int   g_boff[SCAN_BLOCKS];

// ---------------- f32x2 helpers (sm_10x packed fp32 pipe, GEMM only) ----------------
__device__ __forceinline__ ull pack2(float v) {
    ull r; asm("mov.b64 %0, {%1, %1};" : "=l"(r) : "f"(v)); return r;
}
__device__ __forceinline__ void fma2(ull &d, ull a, ull b) {
    asm("fma.rn.f32x2 %0, %1, %2, %0;" : "+l"(d) : "l"(a), "l"(b));
}
__device__ __forceinline__ void unpack2(ull v, float &lo, float &hi) {
    asm("mov.b64 {%0, %1}, %2;" : "=f"(lo), "=f"(hi) : "l"(v));
}

// ---------------- zero per-replay accumulators ----------------
__global__ void zero_kernel() {
    int i = blockIdx.x * blockDim.x + threadIdx.x;
    int stride = gridDim.x * blockDim.x;
    int4* c4 = (int4*)g_cnt_node;
    int4 z4 = make_int4(0, 0, 0, 0);
    for (int k = i; k < N_NODES / 4; k += stride) c4[k] = z4;
    for (int k = i; k < N_GRAPHS * HID; k += stride) g_pool[k] = 0.0f;
}

// ---------------- in-degree histogram: 4 edges per thread ----------------
__global__ void hist_edges_kernel(const int* __restrict__ dst) {
    int i = blockIdx.x * blockDim.x + threadIdx.x;
    if (i < N_EDGES / 4) {
        int4 d4 = ((const int4*)dst)[i];
        atomicAdd(&g_cnt_node[d4.x], 1);
        atomicAdd(&g_cnt_node[d4.y], 1);
        atomicAdd(&g_cnt_node[d4.z], 1);
        atomicAdd(&g_cnt_node[d4.w], 1);
    }
}

// ---------------- per-graph counts via binary search (batch is sorted) --------------
__global__ void gcnt_kernel(const int* __restrict__ batch) {
    __shared__ int starts[N_GRAPHS + 1];
    int g = threadIdx.x;
    if (g <= N_GRAPHS) {
        int lo = 0, hi = N_NODES;
        while (lo < hi) {
            int mid = (lo + hi) >> 1;
            if (batch[mid] < g) lo = mid + 1; else hi = mid;
        }
        starts[g] = lo;
    }
    __syncthreads();
    if (g < N_GRAPHS) g_gcnt[g] = starts[g + 1] - starts[g];
}

// ---------------- parallel scan phase A ----------------
__global__ __launch_bounds__(1024) void scanA_kernel() {
    __shared__ int wsum[32];
    int tid = threadIdx.x, lane = tid & 31, wid = tid >> 5;
    int i = blockIdx.x * 1024 + tid;
    int v = (i < N_NODES) ? g_cnt_node[i] : 0;
    int x = v;
    #pragma unroll
    for (int off = 1; off < 32; off <<= 1) {
        int t = __shfl_up_sync(0xffffffffu, x, off);
        if (lane >= off) x += t;
    }
    if (lane == 31) wsum[wid] = x;
    __syncthreads();
    if (wid == 0) {
        int s = wsum[lane];
        #pragma unroll
        for (int off = 1; off < 32; off <<= 1) {
            int t = __shfl_up_sync(0xffffffffu, s, off);
            if (lane >= off) s += t;
        }
        wsum[lane] = s;
    }
    __syncthreads();
    int woff = (wid == 0) ? 0 : wsum[wid - 1];
    if (i < N_NODES) {
        g_rowptr[i] = woff + (x - v);
        g_dinv[i]   = rsqrtf((float)(v + 1));
    }
    if (tid == 1023) g_bsum[blockIdx.x] = wsum[31];
}

// ---------------- scan phase B ----------------
__global__ void scanB_kernel() {
    __shared__ int wsum[4];
    int tid = threadIdx.x, lane = tid & 31, wid = tid >> 5;
    int v = (tid < SCAN_BLOCKS) ? g_bsum[tid] : 0;
    int x = v;
    #pragma unroll
    for (int off = 1; off < 32; off <<= 1) {
        int t = __shfl_up_sync(0xffffffffu, x, off);
        if (lane >= off) x += t;
    }
    if (lane == 31) wsum[wid] = x;
    __syncthreads();
    int woff = 0;
    for (int w = 0; w < wid; w++) woff += wsum[w];
    if (tid < SCAN_BLOCKS) g_boff[tid] = woff + (x - v);
    if (tid == 0) g_rowptr[N_NODES] = N_EDGES;
}

// ---------------- scan phase C ----------------
__global__ __launch_bounds__(1024) void scanC_kernel() {
    int i = blockIdx.x * 1024 + threadIdx.x;
    if (i < N_NODES) {
        int r = g_rowptr[i] + g_boff[blockIdx.x];
        g_rowptr[i] = r;
        g_cursor[i] = r;
    }
}

// ---------------- CSR fill, 4 edges per thread -------------
__global__ void fill_kernel(const int* __restrict__ src,
                            const int* __restrict__ dst) {
    int i = blockIdx.x * blockDim.x + threadIdx.x;
    if (i < N_EDGES / 4) {
        int4 s4 = ((const int4*)src)[i];
        int4 d4 = ((const int4*)dst)[i];
        int p0 = atomicAdd(&g_cursor[d4.x], 1);
        int p1 = atomicAdd(&g_cursor[d4.y], 1);
        int p2 = atomicAdd(&g_cursor[d4.z], 1);
        int p3 = atomicAdd(&g_cursor[d4.w], 1);
        g_col[p0] = s4.x;
        g_col[p1] = s4.y;
        g_col[p2] = s4.z;
        g_col[p3] = s4.w;
    }
}

// ---- fp32 GEMM (f32x2 pipe): y[r] = X[r] @ W, output packed bf16x2 -----------------
__global__ __launch_bounds__(256) void gemm128_kernel(const float* __restrict__ X,
                                                      const float* __restrict__ W,
                                                      int nrows) {
    __shared__ float As[16][128];
    __shared__ float Bs[16][128];
    int tid = threadIdx.x;
    int tx = tid & 15, ty = tid >> 4;
    int row0 = blockIdx.x * 128;

    ull acc2[8][4];
    #pragma unroll
    for (int j = 0; j < 8; j++)
        #pragma unroll
        for (int i2 = 0; i2 < 4; i2++) acc2[j][i2] = 0ull;

    for (int k0 = 0; k0 < 128; k0 += 16) {
        {
            int r  = tid >> 2;
            int kk = (tid & 3) * 4;
            #pragma unroll
            for (int rr = r; rr < 128; rr += 64) {
                int grow = row0 + rr;
                float4 v = make_float4(0.f, 0.f, 0.f, 0.f);
                if (grow < nrows) v = *(const float4*)(X + (size_t)grow * 128 + k0 + kk);
                As[kk + 0][rr] = v.x; As[kk + 1][rr] = v.y;
                As[kk + 2][rr] = v.z; As[kk + 3][rr] = v.w;
            }
            int k  = tid >> 5;
            int cc = (tid & 31) * 4;
            #pragma unroll
            for (int kk2 = k; kk2 < 16; kk2 += 8) {
                *(float4*)&Bs[kk2][cc] = *(const float4*)(W + (size_t)(k0 + kk2) * 128 + cc);
            }
        }
        __syncthreads();
        #pragma unroll
        for (int k = 0; k < 16; k++) {
            ull a2[4];
            const float* ar = &As[k][0];
            a2[0] = *(const ull*)(ar + ty * 4);
            a2[1] = *(const ull*)(ar + ty * 4 + 2);
            a2[2] = *(const ull*)(ar + 64 + ty * 4);
            a2[3] = *(const ull*)(ar + 64 + ty * 4 + 2);
            ull bb[8];
            #pragma unroll
            for (int j = 0; j < 4; j++) {
                bb[j]     = pack2(Bs[k][tx * 4 + j]);
                bb[4 + j] = pack2(Bs[k][64 + tx * 4 + j]);
            }
            #pragma unroll
            for (int j = 0; j < 8; j++)
                #pragma unroll
                for (int i2 = 0; i2 < 4; i2++)
                    fma2(acc2[j][i2], a2[i2], bb[j]);
        }
        __syncthreads();
    }
    float accf[8][8];
    #pragma unroll
    for (int i2 = 0; i2 < 4; i2++) {
        int iiL = (i2 < 2) ? (i2 * 2) : (4 + (i2 - 2) * 2);
        #pragma unroll
        for (int j = 0; j < 8; j++)
            unpack2(acc2[j][i2], accf[iiL][j], accf[iiL + 1][j]);
    }
    #pragma unroll
    for (int ii = 0; ii < 8; ii++) {
        int r = row0 + ((ii < 4) ? (ty * 4 + ii) : (64 + ty * 4 + (ii - 4)));
        if (r < nrows) {
            __nv_bfloat162 q0 = __floats2bfloat162_rn(accf[ii][0], accf[ii][1]);
            __nv_bfloat162 q1 = __floats2bfloat162_rn(accf[ii][2], accf[ii][3]);
            __nv_bfloat162 q2 = __floats2bfloat162_rn(accf[ii][4], accf[ii][5]);
            __nv_bfloat162 q3 = __floats2bfloat162_rn(accf[ii][6], accf[ii][7]);
            uint2 lo, hi;
            lo.x = *(unsigned*)&q0; lo.y = *(unsigned*)&q1;
            hi.x = *(unsigned*)&q2; hi.y = *(unsigned*)&q3;
            *(uint2*)(g_yb + (size_t)r * 64 + tx * 2)      = lo;
            *(uint2*)(g_yb + (size_t)r * 64 + 32 + tx * 2) = hi;
        }
    }
}

// ---- scale_y: g_yb[v] *= dinv[v] (in place, bf16) ----------------------------------
__global__ __launch_bounds__(256) void scale_y_kernel() {
    int i = blockIdx.x * blockDim.x + threadIdx.x;  // uint2 index; total N_NODES*32
    if (i < N_NODES * 32) {
        int v = i >> 5;
        float dv = g_dinv[v];
        uint2* p = (uint2*)g_yb + i;
        uint2 pk = *p;
        float2 f0 = __bfloat1622float2(*(__nv_bfloat162*)&pk.x);
        float2 f1 = __bfloat1622float2(*(__nv_bfloat162*)&pk.y);
        __nv_bfloat162 q0 = __floats2bfloat162_rn(dv * f0.x, dv * f0.y);
        __nv_bfloat162 q1 = __floats2bfloat162_rn(dv * f1.x, dv * f1.y);
        pk.x = *(unsigned*)&q0;
        pk.y = *(unsigned*)&q1;
        *p = pk;
    }
}

// ---- agg1 (bf16 gather of pre-scaled ys): hs[v] = dinv_v*relu(BN(dv*sum + b1)) -----
__global__ __launch_bounds__(256) void agg1_kernel(const float* __restrict__ b1,
                                                   const float* __restrict__ gamma,
                                                   const float* __restrict__ beta,
                                                   const float* __restrict__ rmean,
                                                   const float* __restrict__ rvar) {
    int gw = (blockIdx.x * blockDim.x + threadIdx.x) >> 5;
    int lane = threadIdx.x & 31;
    if (gw >= N_NODES) return;
    int v = gw;
    int cb = lane * 4;
    const unsigned* __restrict__ ys = (const unsigned*)g_yb;
    float4 acc;
    {
        uint2 pk = *(const uint2*)(ys + (size_t)v * 64 + lane * 2);
        float2 f0 = __bfloat1622float2(*(__nv_bfloat162*)&pk.x);
        float2 f1 = __bfloat1622float2(*(__nv_bfloat162*)&pk.y);
        acc = make_float4(f0.x, f0.y, f1.x, f1.y);   // self term = dinv_v*y_v (pre-scaled)
    }
    int s = g_rowptr[v], e = g_rowptr[v + 1];
    int j = s;
    for (; j + 32 <= e; j += 32) {
        int c = g_col[j + lane];
        #pragma unroll
        for (int t = 0; t < 32; t++) {
            int u = __shfl_sync(0xffffffffu, c, t);
            uint2 pk = *(const uint2*)(ys + (size_t)u * 64 + lane * 2);
            float2 f0 = __bfloat1622float2(*(__nv_bfloat162*)&pk.x);
            float2 f1 = __bfloat1622float2(*(__nv_bfloat162*)&pk.y);
            acc.x += f0.x; acc.y += f0.y; acc.z += f1.x; acc.w += f1.y;
        }
    }
    if (j < e) {
        int c = (j + lane < e) ? g_col[j + lane] : 0;
        int n = e - j;
        for (int t = 0; t < n; t++) {
            int u = __shfl_sync(0xffffffffu, c, t);
            uint2 pk = *(const uint2*)(ys + (size_t)u * 64 + lane * 2);
            float2 f0 = __bfloat1622float2(*(__nv_bfloat162*)&pk.x);
            float2 f1 = __bfloat1622float2(*(__nv_bfloat162*)&pk.y);
            acc.x += f0.x; acc.y += f0.y; acc.z += f1.x; acc.w += f1.y;
        }
    }
    float dv = g_dinv[v];
    float4 bb = *(const float4*)(b1 + cb);
    float4 gm = *(const float4*)(gamma + cb);
    float4 bt = *(const float4*)(beta + cb);
    float4 rm = *(const float4*)(rmean + cb);
    float4 rv = *(const float4*)(rvar + cb);
    float o0, o1, o2, o3;
    {
        float t0 = acc.x * dv + bb.x;
        float t1 = acc.y * dv + bb.y;
        float t2 = acc.z * dv + bb.z;
        float t3 = acc.w * dv + bb.w;
        o0 = dv * fmaxf((t0 - rm.x) * rsqrtf(rv.x + BN_EPS) * gm.x + bt.x, 0.0f);
        o1 = dv * fmaxf((t1 - rm.y) * rsqrtf(rv.y + BN_EPS) * gm.y + bt.y, 0.0f);
        o2 = dv * fmaxf((t2 - rm.z) * rsqrtf(rv.z + BN_EPS) * gm.z + bt.z, 0.0f);
        o3 = dv * fmaxf((t3 - rm.w) * rsqrtf(rv.w + BN_EPS) * gm.w + bt.w, 0.0f);
    }
    __nv_bfloat162 p0 = __floats2bfloat162_rn(o0, o1);
    __nv_bfloat162 p1 = __floats2bfloat162_rn(o2, o3);
    uint2 pk;
    pk.x = *(unsigned*)&p0;
    pk.y = *(unsigned*)&p1;
    *(uint2*)(g_hb + (size_t)v * 64 + lane * 2) = pk;
}

// ---- agg2 (bf16 gather): P[batch[v]] += dinv_v * (sum_u hs_u + hs_v) ---------------
__global__ __launch_bounds__(256) void agg2_kernel(const int* __restrict__ batch) {
    int gw = (blockIdx.x * blockDim.x + threadIdx.x) >> 5;
    int lane = threadIdx.x & 31;
    if (gw >= N_NODES) return;
    int v = gw;
    const unsigned* __restrict__ hb = (const unsigned*)g_hb;
    float4 acc;
    {
        uint2 pk = *(const uint2*)(hb + (size_t)v * 64 + lane * 2);
        float2 f0 = __bfloat1622float2(*(__nv_bfloat162*)&pk.x);
        float2 f1 = __bfloat1622float2(*(__nv_bfloat162*)&pk.y);
        acc = make_float4(f0.x, f0.y, f1.x, f1.y);   // self term = hs_v
    }
    int s = g_rowptr[v], e = g_rowptr[v + 1];
    int j = s;
    for (; j + 32 <= e; j += 32) {
        int c = g_col[j + lane];
        #pragma unroll
        for (int t = 0; t < 32; t++) {
            int u = __shfl_sync(0xffffffffu, c, t);
            uint2 pk = *(const uint2*)(hb + (size_t)u * 64 + lane * 2);
            float2 f0 = __bfloat1622float2(*(__nv_bfloat162*)&pk.x);
            float2 f1 = __bfloat1622float2(*(__nv_bfloat162*)&pk.y);
            acc.x += f0.x; acc.y += f0.y; acc.z += f1.x; acc.w += f1.y;
        }
    }
    if (j < e) {
        int c = (j + lane < e) ? g_col[j + lane] : 0;
        int n = e - j;
        for (int t = 0; t < n; t++) {
            int u = __shfl_sync(0xffffffffu, c, t);
            uint2 pk = *(const uint2*)(hb + (size_t)u * 64 + lane * 2);
            float2 f0 = __bfloat1622float2(*(__nv_bfloat162*)&pk.x);
            float2 f1 = __bfloat1622float2(*(__nv_bfloat162*)&pk.y);
            acc.x += f0.x; acc.y += f0.y; acc.z += f1.x; acc.w += f1.y;
        }
    }
    float dv = g_dinv[v];
    int g = batch[v];
    float* pp = g_pool + (size_t)g * 128 + lane * 4;
    atomicAdd(pp + 0, acc.x * dv);
    atomicAdd(pp + 1, acc.y * dv);
    atomicAdd(pp + 2, acc.z * dv);
    atomicAdd(pp + 3, acc.w * dv);
}

// ---- head: per graph: pooled = (P/cnt)@W2 + b2 ; z = relu(pooled@fw1+fb1) ; out ----
__global__ __launch_bounds__(128) void head_kernel(const float* __restrict__ W2,
                                                   const float* __restrict__ b2,
                                                   const float* __restrict__ fw1,
                                                   const float* __restrict__ fb1,
                                                   const float* __restrict__ cw,
                                                   const float* __restrict__ cbp,
                                                   float* __restrict__ out) {
    __shared__ float Ps[128];
    __shared__ float pooled[128];
    __shared__ float z[64];
    int g = blockIdx.x;
    int j = threadIdx.x;
    float ic = 1.0f / fmaxf((float)g_gcnt[g], 1.0f);
    Ps[j] = g_pool[(size_t)g * 128 + j] * ic;
    __syncthreads();
    float sacc = b2[j];
    #pragma unroll 8
    for (int k = 0; k < 128; k++) sacc = fmaf(Ps[k], W2[(size_t)k * 128 + j], sacc);
    pooled[j] = sacc;
    __syncthreads();
    if (j < 64) {
        float t = fb1[j];
        #pragma unroll 8
        for (int k = 0; k < 128; k++) t = fmaf(pooled[k], fw1[(size_t)k * 64 + j], t);
        z[j] = fmaxf(t, 0.0f);
    }
    __syncthreads();
    if (j < 2) {
        float o = cbp[j];
        #pragma unroll
        for (int jj = 0; jj < 64; jj++) o = fmaf(z[jj], cw[jj * 2 + j], o);
        out[g * 2 + j] = o;
    }
}

// ---------------- launch ----------------
extern "C" void kernel_launch(void* const* d_in, const int* in_sizes, int n_in,
                              void* d_out, int out_size) {
    const float* x     = (const float*)d_in[0];
    const int*   eidx  = (const int*)d_in[1];
    const int*   batch = (const int*)d_in[2];
    const float* W1    = (const float*)d_in[3];
    const float* b1    = (const float*)d_in[4];
    const float* gamma = (const float*)d_in[5];
    const float* beta  = (const float*)d_in[6];
    const float* rmean = (const float*)d_in[7];
    const float* rvar  = (const float*)d_in[8];
    const float* W2    = (const float*)d_in[9];
    const float* b2    = (const float*)d_in[10];
    const float* fw1   = (const float*)d_in[11];
    const float* fb1   = (const float*)d_in[12];
    const float* cw    = (const float*)d_in[13];
    const float* cbv   = (const float*)d_in[14];
    float* out = (float*)d_out;

    const int* src = eidx;
    const int* dst = eidx + N_EDGES;

    cudaStream_t s2;
    cudaStreamCreateWithFlags(&s2, cudaStreamNonBlocking);
    cudaEvent_t e1, e2;
    cudaEventCreateWithFlags(&e1, cudaEventDisableTiming);
    cudaEventCreateWithFlags(&e2, cudaEventDisableTiming);

    // fork: gemm1 + gcnt depend only on inputs
    cudaEventRecord(e1, 0);
    cudaStreamWaitEvent(s2, e1, 0);
    gemm128_kernel<<<(N_NODES + 127) / 128, 256, 0, s2>>>(x, W1, N_NODES);
    gcnt_kernel<<<1, N_GRAPHS + 1, 0, s2>>>(batch);

    // CSR build on main stream, concurrent with gemm1
    zero_kernel<<<256, 256>>>();
    hist_edges_kernel<<<(N_EDGES / 4 + 255) / 256, 256>>>(dst);
    scanA_kernel<<<SCAN_BLOCKS, 1024>>>();
    scanB_kernel<<<1, 128>>>();
    scanC_kernel<<<SCAN_BLOCKS, 1024>>>();
    fill_kernel<<<(N_EDGES / 4 + 255) / 256, 256>>>(src, dst);

    // join
    cudaEventRecord(e2, s2);
    cudaStreamWaitEvent(0, e2, 0);

    // pre-scale y by dinv (kills per-edge dinv loads in agg1)
    scale_y_kernel<<<(N_NODES * 32 + 255) / 256, 256>>>();

    // layer 1 aggregation (bf16 gather + BN + relu), bf16 output
    agg1_kernel<<<(N_NODES + 7) / 8, 256>>>(b1, gamma, beta, rmean, rvar);

    // layer 2 aggregation (bf16 gather) directly into per-graph pool
    agg2_kernel<<<(N_NODES + 7) / 8, 256>>>(batch);

    // head: W2 + mean + MLP
    head_kernel<<<N_GRAPHS, 128>>>(W2, b2, fw1, fb1, cw, cbv, out);

    cudaEventDestroy(e1);
    cudaEventDestroy(e2);
    cudaStreamDestroy(s2);
}